// round 8
// baseline (speedup 1.0000x reference)
#include <cuda_runtime.h>
#include <cuda_bf16.h>
#include <cstdint>

// Problem constants
#define BB 1024
#define RR 8
#define CC 1024
#define DD 16384
#define KK 32
#define THRC 48
#define MAXC 256
#define WINU 6        // refine window in bf16 ULPs below 32nd approx key

// ---------------- device scratch ----------------------------------------------
__device__ __nv_bfloat16 g_h[(size_t)BB * RR * DD];   // 256 MB (ranking only)
__device__ float g_dwT[(size_t)RR * DD * CC];         // 512 MB
__device__ float g_topv[BB * RR * KK];
__device__ int   g_topi[BB * RR * KK];
__device__ __nv_bfloat16 g_xb[(size_t)BB * RR * CC];
__device__ __nv_bfloat16 g_ewb[(size_t)RR * DD * CC];
__device__ unsigned int g_cidx[(size_t)BB * RR * MAXC];   // packed key<<16 | idx
__device__ unsigned int g_ccnt[BB * RR];

__device__ __forceinline__ uint32_t smem_u32(const void* p) {
    uint32_t a;
    asm("{ .reg .u64 t; cvta.to.shared.u64 t, %1; cvt.u32.u64 %0, t; }" : "=r"(a) : "l"(p));
    return a;
}

// ---------------- kernel 0a: x - db -> bf16 ------------------------------------
__global__ __launch_bounds__(256) void conv_x(const float* __restrict__ x,
                                              const float* __restrict__ db) {
    size_t i = (size_t)blockIdx.x * 256 + threadIdx.x;
    size_t e = i * 4;
    int c = (int)(e & (CC - 1));
    int r = (int)((e >> 10) & 7);
    float4 xv = ((const float4*)x)[i];
    float4 dv = *(const float4*)(db + r * CC + c);
    unsigned short h[4];
    h[0] = __bfloat16_as_ushort(__float2bfloat16(xv.x - dv.x));
    h[1] = __bfloat16_as_ushort(__float2bfloat16(xv.y - dv.y));
    h[2] = __bfloat16_as_ushort(__float2bfloat16(xv.z - dv.z));
    h[3] = __bfloat16_as_ushort(__float2bfloat16(xv.w - dv.w));
    uint2 u = {(uint32_t)h[0] | ((uint32_t)h[1] << 16),
               (uint32_t)h[2] | ((uint32_t)h[3] << 16)};
    ((uint2*)g_xb)[i] = u;
}

// ---------------- kernel 0b: ew -> bf16 -----------------------------------------
__global__ __launch_bounds__(256) void conv_ew(const float* __restrict__ ew) {
    size_t i = (size_t)blockIdx.x * 256 + threadIdx.x;
    float4 v = ((const float4*)ew)[i];
    unsigned short h[4];
    h[0] = __bfloat16_as_ushort(__float2bfloat16(v.x));
    h[1] = __bfloat16_as_ushort(__float2bfloat16(v.y));
    h[2] = __bfloat16_as_ushort(__float2bfloat16(v.z));
    h[3] = __bfloat16_as_ushort(__float2bfloat16(v.w));
    uint2 u = {(uint32_t)h[0] | ((uint32_t)h[1] << 16),
               (uint32_t)h[2] | ((uint32_t)h[3] << 16)};
    ((uint2*)g_ewb)[i] = u;
}

// ---------------- kernel 1: transpose decoder_w [R,C,D] -> [R,D,C] -------------
__global__ void transpose_dw(const float* __restrict__ dw) {
    __shared__ float tile[32][33];
    int r  = blockIdx.z;
    int d0 = blockIdx.x * 32;
    int c0 = blockIdx.y * 32;
    const float* src = dw   + (size_t)r * CC * DD;
    float*       dst = g_dwT + (size_t)r * DD * CC;
    int tx = threadIdx.x, ty = threadIdx.y;
#pragma unroll
    for (int i = 0; i < 32; i += 8)
        tile[ty + i][tx] = src[(size_t)(c0 + ty + i) * DD + d0 + tx];
    __syncthreads();
#pragma unroll
    for (int i = 0; i < 32; i += 8)
        dst[(size_t)(d0 + ty + i) * CC + c0 + tx] = tile[tx][ty + i];
}

// ---------------- kernel 2: encode GEMM via mma.sync (bf16, fp32 accum) --------
// BK=64, 3-stage cp.async pipeline; 128B-wide smem rows, XOR-8 swizzle.
#define GBK 64
#define KT (CC / GBK)          // 16
#define STG 3
#define ATILE_B 16384          // 128 * 64 * 2
#define STAGE_B 32768

__device__ __forceinline__ void ldm_x4(uint32_t addr, uint32_t& r0, uint32_t& r1,
                                       uint32_t& r2, uint32_t& r3) {
    asm volatile("ldmatrix.sync.aligned.m8n8.x4.shared.b16 {%0,%1,%2,%3}, [%4];"
                 : "=r"(r0), "=r"(r1), "=r"(r2), "=r"(r3) : "r"(addr));
}
__device__ __forceinline__ void mma16816(float* c, uint32_t a0, uint32_t a1,
                                         uint32_t a2, uint32_t a3,
                                         uint32_t b0, uint32_t b1) {
    asm volatile(
        "mma.sync.aligned.m16n8k16.row.col.f32.bf16.bf16.f32 "
        "{%0,%1,%2,%3}, {%4,%5,%6,%7}, {%8,%9}, {%0,%1,%2,%3};"
        : "+f"(c[0]), "+f"(c[1]), "+f"(c[2]), "+f"(c[3])
        : "r"(a0), "r"(a1), "r"(a2), "r"(a3), "r"(b0), "r"(b1));
}

__global__ __launch_bounds__(256, 2) void encode_gemm_mma(const float* __restrict__ eb) {
    extern __shared__ char smem[];
    uint32_t sb = smem_u32(smem);

    int tid = threadIdx.x, lane = tid & 31, wid = tid >> 5;
    int warp_m = wid >> 2;
    int warp_n = wid & 3;
    int mBase = blockIdx.x * 128;
    int nBase = blockIdx.y * 128;
    int r     = blockIdx.z;

    const __nv_bfloat16* Bb = g_ewb + (size_t)r * DD * CC;

    // cp.async slots: 2048 16B-units per stage; uid = tid + i*256
    uint32_t soff[8];
    const __nv_bfloat16* gbase[8];
#pragma unroll
    for (int i = 0; i < 8; i++) {
        int uid = tid + i * 256;
        int row = (uid & 1023) >> 3;
        int u   = uid & 7;
        bool isA = uid < 1024;
        soff[i] = (isA ? 0u : (uint32_t)ATILE_B) +
                  (uint32_t)(row * 128 + ((u ^ (row & 7)) << 4));
        gbase[i] = isA ? (g_xb + ((size_t)(mBase + row) * RR + r) * CC + u * 8)
                       : (Bb + (size_t)(nBase + row) * CC + u * 8);
    }

    auto issue_stage = [&](int kt, int s) {
        uint32_t sbase = sb + s * STAGE_B;
        int k0 = kt * GBK;
#pragma unroll
        for (int i = 0; i < 8; i++) {
            uint32_t sa = sbase + soff[i];
            const void* g = (const void*)(gbase[i] + k0);
            asm volatile("cp.async.cg.shared.global [%0], [%1], 16;"
                         :: "r"(sa), "l"(g));
        }
        asm volatile("cp.async.commit_group;");
    };

    issue_stage(0, 0);
    issue_stage(1, 1);

    float acc[16][4];
#pragma unroll
    for (int i = 0; i < 16; i++)
#pragma unroll
        for (int j = 0; j < 4; j++) acc[i][j] = 0.f;

    int arow = warp_m * 64 + (lane & 15);
    int ab   = (lane >> 4) & 1;
    int nrow = warp_n * 32 + ((lane >> 4) << 3) + (lane & 7);
    int bb_  = (lane >> 3) & 1;

    int st = 0;                // ring slot of current chunk
    for (int kt = 0; kt < KT; kt++) {
        asm volatile("cp.async.wait_group %0;" :: "n"(STG - 2));
        __syncthreads();
        int nxt = kt + STG - 1;
        int sNxt = st + (STG - 1); if (sNxt >= STG) sNxt -= STG;
        if (nxt < KT) issue_stage(nxt, sNxt);
        else asm volatile("cp.async.commit_group;");

        uint32_t sA = sb + st * STAGE_B;
        uint32_t sB = sA + ATILE_B;

#pragma unroll
        for (int ks = 0; ks < 4; ks++) {
            uint32_t bfr[8];
#pragma unroll
            for (int nfp = 0; nfp < 2; nfp++) {
                int rown = nrow + nfp * 16;
                int unit = ks * 2 + bb_;
                uint32_t addr = sB + rown * 128 + ((unit ^ (rown & 7)) << 4);
                ldm_x4(addr, bfr[nfp * 4 + 0], bfr[nfp * 4 + 1],
                             bfr[nfp * 4 + 2], bfr[nfp * 4 + 3]);
            }
#pragma unroll
            for (int mf = 0; mf < 4; mf++) {
                int rowm = arow + mf * 16;
                int unit = ks * 2 + ab;
                uint32_t addr = sA + rowm * 128 + ((unit ^ (rowm & 7)) << 4);
                uint32_t a0, a1, a2, a3;
                ldm_x4(addr, a0, a1, a2, a3);
#pragma unroll
                for (int nf = 0; nf < 4; nf++)
                    mma16816(acc[mf * 4 + nf], a0, a1, a2, a3,
                             bfr[nf * 2], bfr[nf * 2 + 1]);
            }
        }
        if (++st == STG) st = 0;
    }

    // epilogue: add eb, store bf16 h (ranking only)
    int trow = lane >> 2;
    int tcol = (lane & 3) * 2;
    const float* ebr = eb + (size_t)r * DD;
#pragma unroll
    for (int mf = 0; mf < 4; mf++) {
#pragma unroll
        for (int nf = 0; nf < 4; nf++) {
            int m = mBase + warp_m * 64 + mf * 16 + trow;
            int d = nBase + warp_n * 32 + nf * 8 + tcol;
            float2 ebv = *(const float2*)(ebr + d);
            __nv_bfloat16* h0 = g_h + (size_t)m * (RR * DD) + (size_t)r * DD + d;
            __nv_bfloat16* h1 = h0 + 8 * (size_t)(RR * DD);
            __nv_bfloat162 v0 = __floats2bfloat162_rn(acc[mf * 4 + nf][0] + ebv.x,
                                                      acc[mf * 4 + nf][1] + ebv.y);
            __nv_bfloat162 v1 = __floats2bfloat162_rn(acc[mf * 4 + nf][2] + ebv.x,
                                                      acc[mf * 4 + nf][3] + ebv.y);
            *(__nv_bfloat162*)h0 = v0;
            *(__nv_bfloat162*)h1 = v1;
        }
    }
}

// ---------------- kernel 3a: candidate selection (histogram threshold) ---------
__global__ __launch_bounds__(256) void topk_select() {
    __shared__ unsigned int hist[4096];
    __shared__ unsigned int part[256];
    __shared__ unsigned int s_thrbin, s_cnt;

    int row = blockIdx.x;
    int tid = threadIdx.x;
    int lane = tid & 31, warp = tid >> 5;
    const __nv_bfloat16* hp = g_h + (size_t)row * DD;

    for (int i = tid; i < 4096; i += 256) hist[i] = 0;
    if (tid == 0) s_cnt = 0;
    __syncthreads();

    // pass 1: order-preserving u16 keys; warp-aggregated histogram (12-bit bins)
    for (int i = tid; i < DD / 2; i += 256) {
        uint32_t v = ((const uint32_t*)hp)[i];
        unsigned short a = (unsigned short)(v & 0xFFFFu);
        unsigned short b = (unsigned short)(v >> 16);
        unsigned short ka = (a & 0x8000u) ? (unsigned short)~a : (unsigned short)(a | 0x8000u);
        unsigned short kb = (b & 0x8000u) ? (unsigned short)~b : (unsigned short)(b | 0x8000u);
        unsigned int ba = (unsigned int)(ka >> 4);
        unsigned int bbb = (unsigned int)(kb >> 4);
        unsigned int m1 = __match_any_sync(0xffffffffu, ba);
        if ((m1 & ((1u << lane) - 1u)) == 0u) atomicAdd(&hist[ba], __popc(m1));
        unsigned int m2 = __match_any_sync(0xffffffffu, bbb);
        if ((m2 & ((1u << lane) - 1u)) == 0u) atomicAdd(&hist[bbb], __popc(m2));
    }
    __syncthreads();

    unsigned int psum = 0;
#pragma unroll
    for (int j = 0; j < 16; j++) psum += hist[tid * 16 + j];
    part[tid] = psum;
    __syncthreads();

    if (warp == 0) {
        unsigned int pv[8], s8 = 0;
        int base = lane * 8;
#pragma unroll
        for (int j = 0; j < 8; j++) { pv[j] = part[base + j]; s8 += pv[j]; }
        unsigned int suf = s8;
#pragma unroll
        for (int off = 1; off < 32; off <<= 1) {
            unsigned int o = __shfl_down_sync(0xffffffffu, suf, off);
            if (lane + off < 32) suf += o;
        }
        unsigned int bal = __ballot_sync(0xffffffffu, suf >= THRC);
        int L = 31 - __clz((int)bal);
        if (lane == L) {
            unsigned int acc = suf - s8;
            int seg = base;
            for (int j = 7; j >= 0; j--) {
                if (acc + pv[j] >= THRC) { seg = base + j; break; }
                acc += pv[j];
            }
            int T = seg * 16;
            for (int b2 = seg * 16 + 15; b2 >= seg * 16; b2--) {
                if (acc + hist[b2] >= THRC) { T = b2; break; }
                acc += hist[b2];
            }
            s_thrbin = (unsigned int)T;
        }
    }
    __syncthreads();

    // pass 2: collect packed (key<<16 | idx) candidates
    unsigned int T = s_thrbin;
    unsigned int* crow = g_cidx + (size_t)row * MAXC;
    for (int i = tid; i < DD / 2; i += 256) {
        uint32_t v = ((const uint32_t*)hp)[i];
        unsigned short a = (unsigned short)(v & 0xFFFFu);
        unsigned short b = (unsigned short)(v >> 16);
        unsigned short ka = (a & 0x8000u) ? (unsigned short)~a : (unsigned short)(a | 0x8000u);
        unsigned short kb = (b & 0x8000u) ? (unsigned short)~b : (unsigned short)(b | 0x8000u);
        if ((unsigned int)(ka >> 4) >= T) {
            unsigned int p = atomicAdd(&s_cnt, 1u);
            if (p < MAXC) crow[p] = ((unsigned int)ka << 16) | (unsigned int)(2 * i);
        }
        if ((unsigned int)(kb >> 4) >= T) {
            unsigned int p = atomicAdd(&s_cnt, 1u);
            if (p < MAXC) crow[p] = ((unsigned int)kb << 16) | (unsigned int)(2 * i + 1);
        }
    }
    __syncthreads();
    if (tid == 0) g_ccnt[row] = s_cnt < MAXC ? s_cnt : MAXC;
}

// ---------------- kernel 3b: key-gated compensated refine + rank ---------------
__global__ __launch_bounds__(256) void topk_refine(const float* __restrict__ x,
                                                   const float* __restrict__ ew,
                                                   const float* __restrict__ eb,
                                                   const float* __restrict__ db) {
    __shared__ float xcf[CC];
    __shared__ unsigned int pk[256];
    __shared__ unsigned long long skey[256];

    int row = blockIdx.x;
    int b_  = row >> 3;
    int r_  = row & 7;
    int tid = threadIdx.x;
    int lane = tid & 31, warp = tid >> 5;

    const float* xr  = x  + (size_t)b_ * (RR * CC) + (size_t)r_ * CC;
    const float* dbr = db + r_ * CC;
    for (int c = tid; c < CC; c += 256)
        xcf[c] = xr[c] - dbr[c];

    unsigned int M = g_ccnt[row];
    const unsigned int* crow = g_cidx + (size_t)row * MAXC;
    pk[tid] = (tid < (int)M) ? crow[tid] : 0u;
    skey[tid] = 0ull;
    __syncthreads();

    // bitonic sort 256 packed u32 ascending (key in high bits)
    for (int k = 2; k <= 256; k <<= 1) {
        for (int j2 = k >> 1; j2 > 0; j2 >>= 1) {
            int i = tid, ixj = i ^ j2;
            if (ixj > i) {
                unsigned int ki = pk[i], kj = pk[ixj];
                bool up = ((i & k) == 0);
                if ((ki > kj) == up) { pk[i] = kj; pk[ixj] = ki; }
            }
            __syncthreads();
        }
    }

    // refine threshold: 32nd-largest approx key minus WINU ULPs
    unsigned int k32 = pk[256 - KK] >> 16;
    unsigned int t16 = (k32 > WINU) ? (k32 - WINU) : 0u;

    const float* ewr = ew + (size_t)r_ * DD * CC;

    // compensated fp32 dot for every candidate with key >= t16 (sorted top first)
    for (int jj = warp; jj < 256; jj += 8) {
        unsigned int p = pk[255 - jj];
        if (p == 0u || (p >> 16) < t16) continue;   // uniform per warp
        int d = (int)(p & 0xFFFFu);
        const float* wv = ewr + (size_t)d * CC;
        float s = 0.f, comp = 0.f;
#pragma unroll 4
        for (int c = lane; c < CC; c += 32) {
            float xv = xcf[c];
            float wf = __ldg(wv + c);
            float pr = __fmul_rn(xv, wf);
            float e  = __fmaf_rn(xv, wf, -pr);
            float t  = __fadd_rn(s, pr);
            float z  = __fsub_rn(t, s);
            float lo = __fadd_rn(__fsub_rn(s, __fsub_rn(t, z)), __fsub_rn(pr, z));
            s = t;
            comp = __fadd_rn(comp, __fadd_rn(lo, e));
        }
        double a = (double)s + (double)comp;
#pragma unroll
        for (int off = 16; off > 0; off >>= 1)
            a += __shfl_down_sync(0xffffffffu, a, off);
        if (lane == 0) {
            double v = a + (double)eb[(size_t)r_ * DD + d];
            unsigned long long ub = (unsigned long long)__double_as_longlong(v);
            unsigned long long o = (ub >> 63) ? ~ub : (ub | 0x8000000000000000ull);
            o = (o & ~0x3FFFull) | (unsigned long long)(16383 - d);
            skey[255 - jj] = o;
        }
    }
    __syncthreads();

    // bitonic sort 256 u64 keys ascending (refined values; others = 0)
    for (int k = 2; k <= 256; k <<= 1) {
        for (int j2 = k >> 1; j2 > 0; j2 >>= 1) {
            int i = tid, ixj = i ^ j2;
            if (ixj > i) {
                unsigned long long ki = skey[i], kj = skey[ixj];
                bool up = ((i & k) == 0);
                if ((ki > kj) == up) { skey[i] = kj; skey[ixj] = ki; }
            }
            __syncthreads();
        }
    }

    if (tid < KK) {
        unsigned long long o = skey[255 - tid];
        int d = 16383 - (int)(o & 0x3FFFull);
        unsigned long long vb = o & ~0x3FFFull;
        unsigned long long ub = (vb >> 63) ? (vb & 0x7FFFFFFFFFFFFFFFull) : ~vb;
        double v = __longlong_as_double((long long)ub);
        g_topv[row * KK + tid] = fmaxf((float)v, 0.f);
        g_topi[row * KK + tid] = d;
    }
}

// ---------------- kernel 4: sparse decode --------------------------------------
__global__ __launch_bounds__(256) void decode_kernel(const float* __restrict__ db,
                                                     float* __restrict__ out) {
    __shared__ float sv[KK];
    __shared__ int   si[KK];
    int b = blockIdx.x, r = blockIdx.y;
    int row = b * RR + r;
    int tid = threadIdx.x;
    if (tid < KK) {
        sv[tid] = g_topv[row * KK + tid];
        si[tid] = g_topi[row * KK + tid];
    }
    __syncthreads();

    const float* base = g_dwT + (size_t)r * DD * CC;
    float4 acc = *(const float4*)(db + r * CC + tid * 4);
#pragma unroll 8
    for (int t = 0; t < KK; t++) {
        float v = sv[t];
        float4 w = *(const float4*)(base + (size_t)si[t] * CC + tid * 4);
        acc.x += v * w.x;
        acc.y += v * w.y;
        acc.z += v * w.z;
        acc.w += v * w.w;
    }
    *(float4*)(out + (size_t)b * (RR * CC) + r * CC + tid * 4) = acc;
}

// ---------------- launch ---------------------------------------------------------
extern "C" void kernel_launch(void* const* d_in, const int* in_sizes, int n_in,
                              void* d_out, int out_size) {
    const float* x  = (const float*)d_in[0];
    const float* ew = (const float*)d_in[1];
    const float* eb = (const float*)d_in[2];
    const float* dw = (const float*)d_in[3];
    const float* db = (const float*)d_in[4];
    float* out = (float*)d_out;

    cudaFuncSetAttribute(encode_gemm_mma,
                         cudaFuncAttributeMaxDynamicSharedMemorySize, STG * STAGE_B);

    conv_x<<<(BB * RR * CC / 4) / 256, 256>>>(x, db);
    conv_ew<<<(int)(((size_t)RR * DD * CC / 4) / 256), 256>>>(ew);
    transpose_dw<<<dim3(DD / 32, CC / 32, RR), dim3(32, 8)>>>(dw);
    encode_gemm_mma<<<dim3(BB / 128, DD / 128, RR), 256, STG * STAGE_B>>>(eb);
    topk_select<<<BB * RR, 256>>>();
    topk_refine<<<BB * RR, 256>>>(x, ew, eb, db);
    decode_kernel<<<dim3(BB, RR), 256>>>(db, out);
}

// round 9
// speedup vs baseline: 1.0020x; 1.0020x over previous
#include <cuda_runtime.h>
#include <cuda_bf16.h>
#include <cstdint>

// Problem constants
#define BB 1024
#define RR 8
#define CC 1024
#define DD 16384
#define KK 32
#define THRC 48
#define MAXC 256
#define WINU 6        // refine window in bf16 ULPs below 32nd approx key

// ---------------- device scratch ----------------------------------------------
__device__ __nv_bfloat16 g_h[(size_t)BB * RR * DD];   // 256 MB (ranking only)
__device__ float g_dwT[(size_t)RR * DD * CC];         // 512 MB
__device__ __nv_bfloat16 g_xb[(size_t)BB * RR * CC];
__device__ __nv_bfloat16 g_ewb[(size_t)RR * DD * CC];
__device__ unsigned int g_cidx[(size_t)BB * RR * MAXC];   // packed key<<16 | idx
__device__ unsigned int g_ccnt[BB * RR];

__device__ __forceinline__ uint32_t smem_u32(const void* p) {
    uint32_t a;
    asm("{ .reg .u64 t; cvta.to.shared.u64 t, %1; cvt.u32.u64 %0, t; }" : "=r"(a) : "l"(p));
    return a;
}

// ---------------- kernel 0a: x - db -> bf16 ------------------------------------
__global__ __launch_bounds__(256) void conv_x(const float* __restrict__ x,
                                              const float* __restrict__ db) {
    size_t i = (size_t)blockIdx.x * 256 + threadIdx.x;
    size_t e = i * 4;
    int c = (int)(e & (CC - 1));
    int r = (int)((e >> 10) & 7);
    float4 xv = ((const float4*)x)[i];
    float4 dv = *(const float4*)(db + r * CC + c);
    unsigned short h[4];
    h[0] = __bfloat16_as_ushort(__float2bfloat16(xv.x - dv.x));
    h[1] = __bfloat16_as_ushort(__float2bfloat16(xv.y - dv.y));
    h[2] = __bfloat16_as_ushort(__float2bfloat16(xv.z - dv.z));
    h[3] = __bfloat16_as_ushort(__float2bfloat16(xv.w - dv.w));
    uint2 u = {(uint32_t)h[0] | ((uint32_t)h[1] << 16),
               (uint32_t)h[2] | ((uint32_t)h[3] << 16)};
    ((uint2*)g_xb)[i] = u;
}

// ---------------- kernel 0b: ew -> bf16 -----------------------------------------
__global__ __launch_bounds__(256) void conv_ew(const float* __restrict__ ew) {
    size_t i = (size_t)blockIdx.x * 256 + threadIdx.x;
    float4 v = ((const float4*)ew)[i];
    unsigned short h[4];
    h[0] = __bfloat16_as_ushort(__float2bfloat16(v.x));
    h[1] = __bfloat16_as_ushort(__float2bfloat16(v.y));
    h[2] = __bfloat16_as_ushort(__float2bfloat16(v.z));
    h[3] = __bfloat16_as_ushort(__float2bfloat16(v.w));
    uint2 u = {(uint32_t)h[0] | ((uint32_t)h[1] << 16),
               (uint32_t)h[2] | ((uint32_t)h[3] << 16)};
    ((uint2*)g_ewb)[i] = u;
}

// ---------------- kernel 1: transpose decoder_w [R,C,D] -> [R,D,C] -------------
__global__ void transpose_dw(const float* __restrict__ dw) {
    __shared__ float tile[32][33];
    int r  = blockIdx.z;
    int d0 = blockIdx.x * 32;
    int c0 = blockIdx.y * 32;
    const float* src = dw   + (size_t)r * CC * DD;
    float*       dst = g_dwT + (size_t)r * DD * CC;
    int tx = threadIdx.x, ty = threadIdx.y;
#pragma unroll
    for (int i = 0; i < 32; i += 8)
        tile[ty + i][tx] = src[(size_t)(c0 + ty + i) * DD + d0 + tx];
    __syncthreads();
#pragma unroll
    for (int i = 0; i < 32; i += 8)
        dst[(size_t)(d0 + ty + i) * CC + c0 + tx] = tile[tx][ty + i];
}

// ---------------- kernel 2: encode GEMM via mma.sync (bf16, fp32 accum) --------
// BK=64, 3-stage cp.async pipeline; 128B-wide smem rows, XOR-8 swizzle.
#define GBK 64
#define KT (CC / GBK)          // 16
#define STG 3
#define ATILE_B 16384          // 128 * 64 * 2
#define STAGE_B 32768

__device__ __forceinline__ void ldm_x4(uint32_t addr, uint32_t& r0, uint32_t& r1,
                                       uint32_t& r2, uint32_t& r3) {
    asm volatile("ldmatrix.sync.aligned.m8n8.x4.shared.b16 {%0,%1,%2,%3}, [%4];"
                 : "=r"(r0), "=r"(r1), "=r"(r2), "=r"(r3) : "r"(addr));
}
__device__ __forceinline__ void mma16816(float* c, uint32_t a0, uint32_t a1,
                                         uint32_t a2, uint32_t a3,
                                         uint32_t b0, uint32_t b1) {
    asm volatile(
        "mma.sync.aligned.m16n8k16.row.col.f32.bf16.bf16.f32 "
        "{%0,%1,%2,%3}, {%4,%5,%6,%7}, {%8,%9}, {%0,%1,%2,%3};"
        : "+f"(c[0]), "+f"(c[1]), "+f"(c[2]), "+f"(c[3])
        : "r"(a0), "r"(a1), "r"(a2), "r"(a3), "r"(b0), "r"(b1));
}

__global__ __launch_bounds__(256, 2) void encode_gemm_mma(const float* __restrict__ eb) {
    extern __shared__ char smem[];
    uint32_t sb = smem_u32(smem);

    int tid = threadIdx.x, lane = tid & 31, wid = tid >> 5;
    int warp_m = wid >> 2;
    int warp_n = wid & 3;
    int mBase = blockIdx.x * 128;
    int nBase = blockIdx.y * 128;
    int r     = blockIdx.z;

    const __nv_bfloat16* Bb = g_ewb + (size_t)r * DD * CC;

    uint32_t soff[8];
    const __nv_bfloat16* gbase[8];
#pragma unroll
    for (int i = 0; i < 8; i++) {
        int uid = tid + i * 256;
        int row = (uid & 1023) >> 3;
        int u   = uid & 7;
        bool isA = uid < 1024;
        soff[i] = (isA ? 0u : (uint32_t)ATILE_B) +
                  (uint32_t)(row * 128 + ((u ^ (row & 7)) << 4));
        gbase[i] = isA ? (g_xb + ((size_t)(mBase + row) * RR + r) * CC + u * 8)
                       : (Bb + (size_t)(nBase + row) * CC + u * 8);
    }

    auto issue_stage = [&](int kt, int s) {
        uint32_t sbase = sb + s * STAGE_B;
        int k0 = kt * GBK;
#pragma unroll
        for (int i = 0; i < 8; i++) {
            uint32_t sa = sbase + soff[i];
            const void* g = (const void*)(gbase[i] + k0);
            asm volatile("cp.async.cg.shared.global [%0], [%1], 16;"
                         :: "r"(sa), "l"(g));
        }
        asm volatile("cp.async.commit_group;");
    };

    issue_stage(0, 0);
    issue_stage(1, 1);

    float acc[16][4];
#pragma unroll
    for (int i = 0; i < 16; i++)
#pragma unroll
        for (int j = 0; j < 4; j++) acc[i][j] = 0.f;

    int arow = warp_m * 64 + (lane & 15);
    int ab   = (lane >> 4) & 1;
    int nrow = warp_n * 32 + ((lane >> 4) << 3) + (lane & 7);
    int bb_  = (lane >> 3) & 1;

    int st = 0;
    for (int kt = 0; kt < KT; kt++) {
        asm volatile("cp.async.wait_group %0;" :: "n"(STG - 2));
        __syncthreads();
        int nxt = kt + STG - 1;
        int sNxt = st + (STG - 1); if (sNxt >= STG) sNxt -= STG;
        if (nxt < KT) issue_stage(nxt, sNxt);
        else asm volatile("cp.async.commit_group;");

        uint32_t sA = sb + st * STAGE_B;
        uint32_t sB = sA + ATILE_B;

#pragma unroll
        for (int ks = 0; ks < 4; ks++) {
            uint32_t bfr[8];
#pragma unroll
            for (int nfp = 0; nfp < 2; nfp++) {
                int rown = nrow + nfp * 16;
                int unit = ks * 2 + bb_;
                uint32_t addr = sB + rown * 128 + ((unit ^ (rown & 7)) << 4);
                ldm_x4(addr, bfr[nfp * 4 + 0], bfr[nfp * 4 + 1],
                             bfr[nfp * 4 + 2], bfr[nfp * 4 + 3]);
            }
#pragma unroll
            for (int mf = 0; mf < 4; mf++) {
                int rowm = arow + mf * 16;
                int unit = ks * 2 + ab;
                uint32_t addr = sA + rowm * 128 + ((unit ^ (rowm & 7)) << 4);
                uint32_t a0, a1, a2, a3;
                ldm_x4(addr, a0, a1, a2, a3);
#pragma unroll
                for (int nf = 0; nf < 4; nf++)
                    mma16816(acc[mf * 4 + nf], a0, a1, a2, a3,
                             bfr[nf * 2], bfr[nf * 2 + 1]);
            }
        }
        if (++st == STG) st = 0;
    }

    // epilogue: add eb, store bf16 h (ranking only)
    int trow = lane >> 2;
    int tcol = (lane & 3) * 2;
    const float* ebr = eb + (size_t)r * DD;
#pragma unroll
    for (int mf = 0; mf < 4; mf++) {
#pragma unroll
        for (int nf = 0; nf < 4; nf++) {
            int m = mBase + warp_m * 64 + mf * 16 + trow;
            int d = nBase + warp_n * 32 + nf * 8 + tcol;
            float2 ebv = *(const float2*)(ebr + d);
            __nv_bfloat16* h0 = g_h + (size_t)m * (RR * DD) + (size_t)r * DD + d;
            __nv_bfloat16* h1 = h0 + 8 * (size_t)(RR * DD);
            __nv_bfloat162 v0 = __floats2bfloat162_rn(acc[mf * 4 + nf][0] + ebv.x,
                                                      acc[mf * 4 + nf][1] + ebv.y);
            __nv_bfloat162 v1 = __floats2bfloat162_rn(acc[mf * 4 + nf][2] + ebv.x,
                                                      acc[mf * 4 + nf][3] + ebv.y);
            *(__nv_bfloat162*)h0 = v0;
            *(__nv_bfloat162*)h1 = v1;
        }
    }
}

// ---------------- kernel 3a: candidate selection (histogram threshold) ---------
__global__ __launch_bounds__(256) void topk_select() {
    __shared__ unsigned int hist[4096];
    __shared__ unsigned int part[256];
    __shared__ unsigned int s_thrbin, s_cnt;

    int row = blockIdx.x;
    int tid = threadIdx.x;
    int lane = tid & 31, warp = tid >> 5;
    const __nv_bfloat16* hp = g_h + (size_t)row * DD;

    for (int i = tid; i < 4096; i += 256) hist[i] = 0;
    if (tid == 0) s_cnt = 0;
    __syncthreads();

    for (int i = tid; i < DD / 2; i += 256) {
        uint32_t v = ((const uint32_t*)hp)[i];
        unsigned short a = (unsigned short)(v & 0xFFFFu);
        unsigned short b = (unsigned short)(v >> 16);
        unsigned short ka = (a & 0x8000u) ? (unsigned short)~a : (unsigned short)(a | 0x8000u);
        unsigned short kb = (b & 0x8000u) ? (unsigned short)~b : (unsigned short)(b | 0x8000u);
        unsigned int ba = (unsigned int)(ka >> 4);
        unsigned int bbb = (unsigned int)(kb >> 4);
        unsigned int m1 = __match_any_sync(0xffffffffu, ba);
        if ((m1 & ((1u << lane) - 1u)) == 0u) atomicAdd(&hist[ba], __popc(m1));
        unsigned int m2 = __match_any_sync(0xffffffffu, bbb);
        if ((m2 & ((1u << lane) - 1u)) == 0u) atomicAdd(&hist[bbb], __popc(m2));
    }
    __syncthreads();

    unsigned int psum = 0;
#pragma unroll
    for (int j = 0; j < 16; j++) psum += hist[tid * 16 + j];
    part[tid] = psum;
    __syncthreads();

    if (warp == 0) {
        unsigned int pv[8], s8 = 0;
        int base = lane * 8;
#pragma unroll
        for (int j = 0; j < 8; j++) { pv[j] = part[base + j]; s8 += pv[j]; }
        unsigned int suf = s8;
#pragma unroll
        for (int off = 1; off < 32; off <<= 1) {
            unsigned int o = __shfl_down_sync(0xffffffffu, suf, off);
            if (lane + off < 32) suf += o;
        }
        unsigned int bal = __ballot_sync(0xffffffffu, suf >= THRC);
        int L = 31 - __clz((int)bal);
        if (lane == L) {
            unsigned int acc = suf - s8;
            int seg = base;
            for (int j = 7; j >= 0; j--) {
                if (acc + pv[j] >= THRC) { seg = base + j; break; }
                acc += pv[j];
            }
            int T = seg * 16;
            for (int b2 = seg * 16 + 15; b2 >= seg * 16; b2--) {
                if (acc + hist[b2] >= THRC) { T = b2; break; }
                acc += hist[b2];
            }
            s_thrbin = (unsigned int)T;
        }
    }
    __syncthreads();

    unsigned int T = s_thrbin;
    unsigned int* crow = g_cidx + (size_t)row * MAXC;
    for (int i = tid; i < DD / 2; i += 256) {
        uint32_t v = ((const uint32_t*)hp)[i];
        unsigned short a = (unsigned short)(v & 0xFFFFu);
        unsigned short b = (unsigned short)(v >> 16);
        unsigned short ka = (a & 0x8000u) ? (unsigned short)~a : (unsigned short)(a | 0x8000u);
        unsigned short kb = (b & 0x8000u) ? (unsigned short)~b : (unsigned short)(b | 0x8000u);
        if ((unsigned int)(ka >> 4) >= T) {
            unsigned int p = atomicAdd(&s_cnt, 1u);
            if (p < MAXC) crow[p] = ((unsigned int)ka << 16) | (unsigned int)(2 * i);
        }
        if ((unsigned int)(kb >> 4) >= T) {
            unsigned int p = atomicAdd(&s_cnt, 1u);
            if (p < MAXC) crow[p] = ((unsigned int)kb << 16) | (unsigned int)(2 * i + 1);
        }
    }
    __syncthreads();
    if (tid == 0) g_ccnt[row] = s_cnt < MAXC ? s_cnt : MAXC;
}

// ---------------- kernel 3b: key-gated refine + rank + fused sparse decode -----
__global__ __launch_bounds__(256) void topk_refine_decode(const float* __restrict__ x,
                                                          const float* __restrict__ ew,
                                                          const float* __restrict__ eb,
                                                          const float* __restrict__ db,
                                                          float* __restrict__ out) {
    __shared__ float xcf[CC];
    __shared__ unsigned int pk[256];
    __shared__ unsigned long long skey[256];
    __shared__ float sv[KK];
    __shared__ int   si[KK];

    int row = blockIdx.x;
    int b_  = row >> 3;
    int r_  = row & 7;
    int tid = threadIdx.x;
    int lane = tid & 31, warp = tid >> 5;

    const float* xr  = x  + (size_t)b_ * (RR * CC) + (size_t)r_ * CC;
    const float* dbr = db + r_ * CC;
    for (int c = tid; c < CC; c += 256)
        xcf[c] = xr[c] - dbr[c];

    unsigned int M = g_ccnt[row];
    const unsigned int* crow = g_cidx + (size_t)row * MAXC;
    pk[tid] = (tid < (int)M) ? crow[tid] : 0u;
    skey[tid] = 0ull;
    __syncthreads();

    // bitonic sort 256 packed u32 ascending (approx key in high bits)
    for (int k = 2; k <= 256; k <<= 1) {
        for (int j2 = k >> 1; j2 > 0; j2 >>= 1) {
            int i = tid, ixj = i ^ j2;
            if (ixj > i) {
                unsigned int ki = pk[i], kj = pk[ixj];
                bool up = ((i & k) == 0);
                if ((ki > kj) == up) { pk[i] = kj; pk[ixj] = ki; }
            }
            __syncthreads();
        }
    }

    unsigned int k32 = pk[256 - KK] >> 16;
    unsigned int t16 = (k32 > WINU) ? (k32 - WINU) : 0u;

    const float* ewr = ew + (size_t)r_ * DD * CC;

    // compensated fp32 dot for candidates with key >= t16
    for (int jj = warp; jj < 256; jj += 8) {
        unsigned int p = pk[255 - jj];
        if (p == 0u || (p >> 16) < t16) continue;
        int d = (int)(p & 0xFFFFu);
        const float* wv = ewr + (size_t)d * CC;
        float s = 0.f, comp = 0.f;
#pragma unroll 4
        for (int c = lane; c < CC; c += 32) {
            float xv = xcf[c];
            float wf = __ldg(wv + c);
            float pr = __fmul_rn(xv, wf);
            float e  = __fmaf_rn(xv, wf, -pr);
            float t  = __fadd_rn(s, pr);
            float z  = __fsub_rn(t, s);
            float lo = __fadd_rn(__fsub_rn(s, __fsub_rn(t, z)), __fsub_rn(pr, z));
            s = t;
            comp = __fadd_rn(comp, __fadd_rn(lo, e));
        }
        double a = (double)s + (double)comp;
#pragma unroll
        for (int off = 16; off > 0; off >>= 1)
            a += __shfl_down_sync(0xffffffffu, a, off);
        if (lane == 0) {
            double v = a + (double)eb[(size_t)r_ * DD + d];
            unsigned long long ub = (unsigned long long)__double_as_longlong(v);
            unsigned long long o = (ub >> 63) ? ~ub : (ub | 0x8000000000000000ull);
            o = (o & ~0x3FFFull) | (unsigned long long)(16383 - d);
            skey[255 - jj] = o;
        }
    }
    __syncthreads();

    // bitonic sort 256 u64 keys ascending
    for (int k = 2; k <= 256; k <<= 1) {
        for (int j2 = k >> 1; j2 > 0; j2 >>= 1) {
            int i = tid, ixj = i ^ j2;
            if (ixj > i) {
                unsigned long long ki = skey[i], kj = skey[ixj];
                bool up = ((i & k) == 0);
                if ((ki > kj) == up) { skey[i] = kj; skey[ixj] = ki; }
            }
            __syncthreads();
        }
    }

    if (tid < KK) {
        unsigned long long o = skey[255 - tid];
        int d = 16383 - (int)(o & 0x3FFFull);
        unsigned long long vb = o & ~0x3FFFull;
        unsigned long long ub = (vb >> 63) ? (vb & 0x7FFFFFFFFFFFFFFFull) : ~vb;
        double v = __longlong_as_double((long long)ub);
        sv[tid] = fmaxf((float)v, 0.f);
        si[tid] = d;
    }
    __syncthreads();

    // fused sparse decode: out[b,r,c] = db[r,c] + sum_t sv[t] * dwT[r, si[t], c]
    const float* base = g_dwT + (size_t)r_ * DD * CC;
    float4 acc4 = *(const float4*)(dbr + tid * 4);
#pragma unroll 8
    for (int t = 0; t < KK; t++) {
        float v = sv[t];
        float4 w = *(const float4*)(base + (size_t)si[t] * CC + tid * 4);
        acc4.x += v * w.x;
        acc4.y += v * w.y;
        acc4.z += v * w.z;
        acc4.w += v * w.w;
    }
    *(float4*)(out + (size_t)b_ * (RR * CC) + r_ * CC + tid * 4) = acc4;
}

// ---------------- launch ---------------------------------------------------------
extern "C" void kernel_launch(void* const* d_in, const int* in_sizes, int n_in,
                              void* d_out, int out_size) {
    const float* x  = (const float*)d_in[0];
    const float* ew = (const float*)d_in[1];
    const float* eb = (const float*)d_in[2];
    const float* dw = (const float*)d_in[3];
    const float* db = (const float*)d_in[4];
    float* out = (float*)d_out;

    // lazy one-time side stream + events (host resources only; no device mem)
    static cudaStream_t s_tr = nullptr;
    static cudaEvent_t evRoot = nullptr, evT = nullptr;
    if (s_tr == nullptr) {
        cudaStreamCreateWithFlags(&s_tr, cudaStreamNonBlocking);
        cudaEventCreateWithFlags(&evRoot, cudaEventDisableTiming);
        cudaEventCreateWithFlags(&evT, cudaEventDisableTiming);
        cudaFuncSetAttribute(encode_gemm_mma,
                             cudaFuncAttributeMaxDynamicSharedMemorySize,
                             STG * STAGE_B);
    }

    // fork: transpose_dw runs concurrently with the conv/GEMM/select chain
    cudaEventRecord(evRoot, 0);
    cudaStreamWaitEvent(s_tr, evRoot, 0);
    transpose_dw<<<dim3(DD / 32, CC / 32, RR), dim3(32, 8), 0, s_tr>>>(dw);
    cudaEventRecord(evT, s_tr);

    conv_x<<<(BB * RR * CC / 4) / 256, 256>>>(x, db);
    conv_ew<<<(int)(((size_t)RR * DD * CC / 4) / 256), 256>>>(ew);
    encode_gemm_mma<<<dim3(BB / 128, DD / 128, RR), 256, STG * STAGE_B>>>(eb);
    topk_select<<<BB * RR, 256>>>();

    // join: fused refine+decode needs g_dwT
    cudaStreamWaitEvent(0, evT, 0);
    topk_refine_decode<<<BB * RR, 256>>>(x, ew, eb, db, out);
}

// round 11
// speedup vs baseline: 1.0275x; 1.0255x over previous
#include <cuda_runtime.h>
#include <cuda_bf16.h>
#include <cuda_fp16.h>
#include <cstdint>

// Problem constants
#define BB 1024
#define RR 8
#define CC 1024
#define DD 16384
#define KK 32
#define THRC 48
#define MAXC 256
#define WINU 6

// ---------------- device scratch ----------------------------------------------
__device__ __nv_bfloat16 g_h[(size_t)BB * RR * DD];      // 256 MB (ranking only)
__device__ __half g_dwT[(size_t)RR * DD * CC];           // 256 MB fp16 [R,D,C]
__device__ __nv_bfloat16 g_xb[(size_t)BB * RR * CC];
__device__ __nv_bfloat16 g_ewb[(size_t)RR * DD * CC];

__device__ __forceinline__ uint32_t smem_u32(const void* p) {
    uint32_t a;
    asm("{ .reg .u64 t; cvta.to.shared.u64 t, %1; cvt.u32.u64 %0, t; }" : "=r"(a) : "l"(p));
    return a;
}

// ---------------- kernel 0: fused prep (conv_ew | transpose_dw->fp16 | conv_x) --
#define EW_BLOCKS ((int)(((size_t)RR * DD * CC / 4) / 256))     // 131072
#define TR_BLOCKS ((DD / 32) * (CC / 64) * RR)                  // 65536
#define X_BLOCKS  ((BB * RR * CC / 4) / 256)                    // 8192

__global__ __launch_bounds__(256) void prep_kernel(const float* __restrict__ ew,
                                                   const float* __restrict__ dw,
                                                   const float* __restrict__ x,
                                                   const float* __restrict__ db) {
    __shared__ float tile[32][65];
    int bid = blockIdx.x;
    int tid = threadIdx.x;

    if (bid < EW_BLOCKS) {
        // ---- conv_ew: fp32 -> bf16 ----
        size_t i = (size_t)bid * 256 + tid;
        float4 v = ((const float4*)ew)[i];
        unsigned short h[4];
        h[0] = __bfloat16_as_ushort(__float2bfloat16(v.x));
        h[1] = __bfloat16_as_ushort(__float2bfloat16(v.y));
        h[2] = __bfloat16_as_ushort(__float2bfloat16(v.z));
        h[3] = __bfloat16_as_ushort(__float2bfloat16(v.w));
        uint2 u = {(uint32_t)h[0] | ((uint32_t)h[1] << 16),
                   (uint32_t)h[2] | ((uint32_t)h[3] << 16)};
        ((uint2*)g_ewb)[i] = u;
    } else if (bid < EW_BLOCKS + TR_BLOCKS) {
        // ---- transpose dw [R,C,D] -> fp16 dwT [R,D,C]; tile 32(d) x 64(c) ----
        int bid2 = bid - EW_BLOCKS;
        int r   = bid2 >> 13;              // 8192 blocks per r
        int rem = bid2 & 8191;
        int d0  = (rem & 511) * 32;
        int c0  = (rem >> 9) * 64;
        const float* src = dw + (size_t)r * CC * DD;
        __half* dst = g_dwT + (size_t)r * DD * CC;
        int tx = tid & 31, ty = tid >> 5;  // 32 x 8
#pragma unroll
        for (int i = 0; i < 64; i += 8)
            tile[tx][ty + i] = src[(size_t)(c0 + ty + i) * DD + d0 + tx];
        __syncthreads();
#pragma unroll
        for (int w = 0; w < 4; w++) {
            int uid = tid + w * 256;
            int drow = uid >> 5;           // 0..31
            int cp   = uid & 31;           // 0..31 (half2 pairs)
            __half2 hv = __floats2half2_rn(tile[drow][2 * cp],
                                           tile[drow][2 * cp + 1]);
            *(__half2*)(dst + (size_t)(d0 + drow) * CC + c0 + 2 * cp) = hv;
        }
    } else {
        // ---- conv_x: (x - db) -> bf16 ----
        int bid2 = bid - (EW_BLOCKS + TR_BLOCKS);
        size_t i = (size_t)bid2 * 256 + tid;
        size_t e = i * 4;
        int c = (int)(e & (CC - 1));
        int r = (int)((e >> 10) & 7);
        float4 xv = ((const float4*)x)[i];
        float4 dv = *(const float4*)(db + r * CC + c);
        unsigned short h[4];
        h[0] = __bfloat16_as_ushort(__float2bfloat16(xv.x - dv.x));
        h[1] = __bfloat16_as_ushort(__float2bfloat16(xv.y - dv.y));
        h[2] = __bfloat16_as_ushort(__float2bfloat16(xv.z - dv.z));
        h[3] = __bfloat16_as_ushort(__float2bfloat16(xv.w - dv.w));
        uint2 u = {(uint32_t)h[0] | ((uint32_t)h[1] << 16),
                   (uint32_t)h[2] | ((uint32_t)h[3] << 16)};
        ((uint2*)g_xb)[i] = u;
    }
}

// ---------------- kernel 2: encode GEMM via mma.sync (bf16, fp32 accum) --------
#define GBK 64
#define KT (CC / GBK)
#define STG 3
#define ATILE_B 16384
#define STAGE_B 32768

__device__ __forceinline__ void ldm_x4(uint32_t addr, uint32_t& r0, uint32_t& r1,
                                       uint32_t& r2, uint32_t& r3) {
    asm volatile("ldmatrix.sync.aligned.m8n8.x4.shared.b16 {%0,%1,%2,%3}, [%4];"
                 : "=r"(r0), "=r"(r1), "=r"(r2), "=r"(r3) : "r"(addr));
}
__device__ __forceinline__ void mma16816(float* c, uint32_t a0, uint32_t a1,
                                         uint32_t a2, uint32_t a3,
                                         uint32_t b0, uint32_t b1) {
    asm volatile(
        "mma.sync.aligned.m16n8k16.row.col.f32.bf16.bf16.f32 "
        "{%0,%1,%2,%3}, {%4,%5,%6,%7}, {%8,%9}, {%0,%1,%2,%3};"
        : "+f"(c[0]), "+f"(c[1]), "+f"(c[2]), "+f"(c[3])
        : "r"(a0), "r"(a1), "r"(a2), "r"(a3), "r"(b0), "r"(b1));
}

__global__ __launch_bounds__(256, 2) void encode_gemm_mma(const float* __restrict__ eb) {
    extern __shared__ char smem[];
    uint32_t sb = smem_u32(smem);

    int tid = threadIdx.x, lane = tid & 31, wid = tid >> 5;
    int warp_m = wid >> 2;
    int warp_n = wid & 3;
    int mBase = blockIdx.x * 128;
    int nBase = blockIdx.y * 128;
    int r     = blockIdx.z;

    const __nv_bfloat16* Bb = g_ewb + (size_t)r * DD * CC;

    uint32_t soff[8];
    const __nv_bfloat16* gbase[8];
#pragma unroll
    for (int i = 0; i < 8; i++) {
        int uid = tid + i * 256;
        int row = (uid & 1023) >> 3;
        int u   = uid & 7;
        bool isA = uid < 1024;
        soff[i] = (isA ? 0u : (uint32_t)ATILE_B) +
                  (uint32_t)(row * 128 + ((u ^ (row & 7)) << 4));
        gbase[i] = isA ? (g_xb + ((size_t)(mBase + row) * RR + r) * CC + u * 8)
                       : (Bb + (size_t)(nBase + row) * CC + u * 8);
    }

    auto issue_stage = [&](int kt, int s) {
        uint32_t sbase = sb + s * STAGE_B;
        int k0 = kt * GBK;
#pragma unroll
        for (int i = 0; i < 8; i++) {
            uint32_t sa = sbase + soff[i];
            const void* g = (const void*)(gbase[i] + k0);
            asm volatile("cp.async.cg.shared.global [%0], [%1], 16;"
                         :: "r"(sa), "l"(g));
        }
        asm volatile("cp.async.commit_group;");
    };

    issue_stage(0, 0);
    issue_stage(1, 1);

    float acc[16][4];
#pragma unroll
    for (int i = 0; i < 16; i++)
#pragma unroll
        for (int j = 0; j < 4; j++) acc[i][j] = 0.f;

    int arow = warp_m * 64 + (lane & 15);
    int ab   = (lane >> 4) & 1;
    int nrow = warp_n * 32 + ((lane >> 4) << 3) + (lane & 7);
    int bb_  = (lane >> 3) & 1;

    int st = 0;
    for (int kt = 0; kt < KT; kt++) {
        asm volatile("cp.async.wait_group %0;" :: "n"(STG - 2));
        __syncthreads();
        int nxt = kt + STG - 1;
        int sNxt = st + (STG - 1); if (sNxt >= STG) sNxt -= STG;
        if (nxt < KT) issue_stage(nxt, sNxt);
        else asm volatile("cp.async.commit_group;");

        uint32_t sA = sb + st * STAGE_B;
        uint32_t sB = sA + ATILE_B;

#pragma unroll
        for (int ks = 0; ks < 4; ks++) {
            uint32_t bfr[8];
#pragma unroll
            for (int nfp = 0; nfp < 2; nfp++) {
                int rown = nrow + nfp * 16;
                int unit = ks * 2 + bb_;
                uint32_t addr = sB + rown * 128 + ((unit ^ (rown & 7)) << 4);
                ldm_x4(addr, bfr[nfp * 4 + 0], bfr[nfp * 4 + 1],
                             bfr[nfp * 4 + 2], bfr[nfp * 4 + 3]);
            }
#pragma unroll
            for (int mf = 0; mf < 4; mf++) {
                int rowm = arow + mf * 16;
                int unit = ks * 2 + ab;
                uint32_t addr = sA + rowm * 128 + ((unit ^ (rowm & 7)) << 4);
                uint32_t a0, a1, a2, a3;
                ldm_x4(addr, a0, a1, a2, a3);
#pragma unroll
                for (int nf = 0; nf < 4; nf++)
                    mma16816(acc[mf * 4 + nf], a0, a1, a2, a3,
                             bfr[nf * 2], bfr[nf * 2 + 1]);
            }
        }
        if (++st == STG) st = 0;
    }

    int trow = lane >> 2;
    int tcol = (lane & 3) * 2;
    const float* ebr = eb + (size_t)r * DD;
#pragma unroll
    for (int mf = 0; mf < 4; mf++) {
#pragma unroll
        for (int nf = 0; nf < 4; nf++) {
            int m = mBase + warp_m * 64 + mf * 16 + trow;
            int d = nBase + warp_n * 32 + nf * 8 + tcol;
            float2 ebv = *(const float2*)(ebr + d);
            __nv_bfloat16* h0 = g_h + (size_t)m * (RR * DD) + (size_t)r * DD + d;
            __nv_bfloat16* h1 = h0 + 8 * (size_t)(RR * DD);
            __nv_bfloat162 v0 = __floats2bfloat162_rn(acc[mf * 4 + nf][0] + ebv.x,
                                                      acc[mf * 4 + nf][1] + ebv.y);
            __nv_bfloat162 v1 = __floats2bfloat162_rn(acc[mf * 4 + nf][2] + ebv.x,
                                                      acc[mf * 4 + nf][3] + ebv.y);
            *(__nv_bfloat162*)h0 = v0;
            *(__nv_bfloat162*)h1 = v1;
        }
    }
}

// ---------------- kernel 3: fused select + refine + rank + decode --------------
// dynamic smem layout (52224 B):
//   [0, 32768)      u16 keys[16384]
//   [32768, 49152)  u32 hist[4096]   (xcf float[1024] overlaid after threshold)
//   [49152, 50176)  u32 pk[256]
//   [50176, 52224)  u64 skey[256]
__global__ __launch_bounds__(256) void topk_fused(const float* __restrict__ x,
                                                  const float* __restrict__ ew,
                                                  const float* __restrict__ eb,
                                                  const float* __restrict__ db,
                                                  float* __restrict__ out) {
    extern __shared__ char sm[];
    unsigned short* keys = (unsigned short*)sm;
    unsigned int*   hist = (unsigned int*)(sm + 32768);
    float*          xcf  = (float*)(sm + 32768);
    unsigned int*   pk   = (unsigned int*)(sm + 49152);
    unsigned long long* skey = (unsigned long long*)(sm + 50176);

    __shared__ unsigned int part[256];
    __shared__ unsigned int s_thrbin, s_cnt;
    __shared__ float sv[KK];
    __shared__ int   si[KK];

    int row = blockIdx.x;
    int b_  = row >> 3;
    int r_  = row & 7;
    int tid = threadIdx.x;
    int lane = tid & 31, warp = tid >> 5;
    const __nv_bfloat16* hp = g_h + (size_t)row * DD;

    for (int i = tid; i < 4096; i += 256) hist[i] = 0;
    if (tid == 0) s_cnt = 0;
    __syncthreads();

    // keys + warp-aggregated histogram (single pass over h)
    for (int i = tid; i < DD / 2; i += 256) {
        uint32_t v = ((const uint32_t*)hp)[i];
        unsigned short a = (unsigned short)(v & 0xFFFFu);
        unsigned short b = (unsigned short)(v >> 16);
        unsigned short ka = (a & 0x8000u) ? (unsigned short)~a : (unsigned short)(a | 0x8000u);
        unsigned short kb = (b & 0x8000u) ? (unsigned short)~b : (unsigned short)(b | 0x8000u);
        keys[2 * i]     = ka;
        keys[2 * i + 1] = kb;
        unsigned int ba = (unsigned int)(ka >> 4);
        unsigned int bbb = (unsigned int)(kb >> 4);
        unsigned int m1 = __match_any_sync(0xffffffffu, ba);
        if ((m1 & ((1u << lane) - 1u)) == 0u) atomicAdd(&hist[ba], __popc(m1));
        unsigned int m2 = __match_any_sync(0xffffffffu, bbb);
        if ((m2 & ((1u << lane) - 1u)) == 0u) atomicAdd(&hist[bbb], __popc(m2));
    }
    __syncthreads();

    unsigned int psum = 0;
#pragma unroll
    for (int j = 0; j < 16; j++) psum += hist[tid * 16 + j];
    part[tid] = psum;
    __syncthreads();

    if (warp == 0) {
        unsigned int pv[8], s8 = 0;
        int base = lane * 8;
#pragma unroll
        for (int j = 0; j < 8; j++) { pv[j] = part[base + j]; s8 += pv[j]; }
        unsigned int suf = s8;
#pragma unroll
        for (int off = 1; off < 32; off <<= 1) {
            unsigned int o = __shfl_down_sync(0xffffffffu, suf, off);
            if (lane + off < 32) suf += o;
        }
        unsigned int bal = __ballot_sync(0xffffffffu, suf >= THRC);
        int L = 31 - __clz((int)bal);
        if (lane == L) {
            unsigned int acc = suf - s8;
            int seg = base;
            for (int j = 7; j >= 0; j--) {
                if (acc + pv[j] >= THRC) { seg = base + j; break; }
                acc += pv[j];
            }
            int T = seg * 16;
            for (int b2 = seg * 16 + 15; b2 >= seg * 16; b2--) {
                if (acc + hist[b2] >= THRC) { T = b2; break; }
                acc += hist[b2];
            }
            s_thrbin = (unsigned int)T;
        }
    }
    __syncthreads();

    // collect candidates from smem keys; overlay xcf over dead hist region
    unsigned int T = s_thrbin;
    const float* xr  = x  + (size_t)b_ * (RR * CC) + (size_t)r_ * CC;
    const float* dbr = db + r_ * CC;
    for (int c = tid; c < CC; c += 256)
        xcf[c] = xr[c] - dbr[c];
    pk[tid] = 0u;
    skey[tid] = 0ull;
    __syncthreads();
    for (int i = tid; i < DD; i += 256) {
        unsigned int k = (unsigned int)keys[i];
        if ((k >> 4) >= T) {
            unsigned int p = atomicAdd(&s_cnt, 1u);
            if (p < MAXC) pk[p] = (k << 16) | (unsigned int)i;
        }
    }
    __syncthreads();

    // bitonic sort 256 packed u32 ascending (approx key in high bits)
    for (int k = 2; k <= 256; k <<= 1) {
        for (int j2 = k >> 1; j2 > 0; j2 >>= 1) {
            int i = tid, ixj = i ^ j2;
            if (ixj > i) {
                unsigned int ki = pk[i], kj = pk[ixj];
                bool up = ((i & k) == 0);
                if ((ki > kj) == up) { pk[i] = kj; pk[ixj] = ki; }
            }
            __syncthreads();
        }
    }

    unsigned int k32 = pk[256 - KK] >> 16;
    unsigned int t16 = (k32 > WINU) ? (k32 - WINU) : 0u;

    const float* ewr = ew + (size_t)r_ * DD * CC;

    // compensated fp32 dot for candidates with key >= t16
    for (int jj = warp; jj < 256; jj += 8) {
        unsigned int p = pk[255 - jj];
        if (p == 0u || (p >> 16) < t16) continue;
        int d = (int)(p & 0xFFFFu);
        const float* wv = ewr + (size_t)d * CC;
        float s = 0.f, comp = 0.f;
#pragma unroll 4
        for (int c = lane; c < CC; c += 32) {
            float xv = xcf[c];
            float wf = __ldg(wv + c);
            float pr = __fmul_rn(xv, wf);
            float e  = __fmaf_rn(xv, wf, -pr);
            float t  = __fadd_rn(s, pr);
            float z  = __fsub_rn(t, s);
            float lo = __fadd_rn(__fsub_rn(s, __fsub_rn(t, z)), __fsub_rn(pr, z));
            s = t;
            comp = __fadd_rn(comp, __fadd_rn(lo, e));
        }
        double a = (double)s + (double)comp;
#pragma unroll
        for (int off = 16; off > 0; off >>= 1)
            a += __shfl_down_sync(0xffffffffu, a, off);
        if (lane == 0) {
            double v = a + (double)eb[(size_t)r_ * DD + d];
            unsigned long long ub = (unsigned long long)__double_as_longlong(v);
            unsigned long long o = (ub >> 63) ? ~ub : (ub | 0x8000000000000000ull);
            o = (o & ~0x3FFFull) | (unsigned long long)(16383 - d);
            skey[255 - jj] = o;
        }
    }
    __syncthreads();

    // bitonic sort 256 u64 keys ascending
    for (int k = 2; k <= 256; k <<= 1) {
        for (int j2 = k >> 1; j2 > 0; j2 >>= 1) {
            int i = tid, ixj = i ^ j2;
            if (ixj > i) {
                unsigned long long ki = skey[i], kj = skey[ixj];
                bool up = ((i & k) == 0);
                if ((ki > kj) == up) { skey[i] = kj; skey[ixj] = ki; }
            }
            __syncthreads();
        }
    }

    if (tid < KK) {
        unsigned long long o = skey[255 - tid];
        int d = 16383 - (int)(o & 0x3FFFull);
        unsigned long long vb = o & ~0x3FFFull;
        unsigned long long ub = (vb >> 63) ? (vb & 0x7FFFFFFFFFFFFFFFull) : ~vb;
        double v = __longlong_as_double((long long)ub);
        sv[tid] = fmaxf((float)v, 0.f);
        si[tid] = d;
    }
    __syncthreads();

    // fused sparse decode from fp16 dwT
    const __half* base = g_dwT + (size_t)r_ * DD * CC;
    float4 acc4 = *(const float4*)(dbr + tid * 4);
#pragma unroll 8
    for (int t = 0; t < KK; t++) {
        float v = sv[t];
        const __half2* wp = (const __half2*)(base + (size_t)si[t] * CC + tid * 4);
        __half2 w01 = wp[0];
        __half2 w23 = wp[1];
        float2 f01 = __half22float2(w01);
        float2 f23 = __half22float2(w23);
        acc4.x += v * f01.x;
        acc4.y += v * f01.y;
        acc4.z += v * f23.x;
        acc4.w += v * f23.y;
    }
    *(float4*)(out + (size_t)b_ * (RR * CC) + r_ * CC + tid * 4) = acc4;
}

// ---------------- launch (single stream, 3 kernels) ------------------------------
extern "C" void kernel_launch(void* const* d_in, const int* in_sizes, int n_in,
                              void* d_out, int out_size) {
    const float* x  = (const float*)d_in[0];
    const float* ew = (const float*)d_in[1];
    const float* eb = (const float*)d_in[2];
    const float* dw = (const float*)d_in[3];
    const float* db = (const float*)d_in[4];
    float* out = (float*)d_out;

    cudaFuncSetAttribute(encode_gemm_mma,
                         cudaFuncAttributeMaxDynamicSharedMemorySize, STG * STAGE_B);
    cudaFuncSetAttribute(topk_fused,
                         cudaFuncAttributeMaxDynamicSharedMemorySize, 52224);

    prep_kernel<<<EW_BLOCKS + TR_BLOCKS + X_BLOCKS, 256>>>(ew, dw, x, db);
    encode_gemm_mma<<<dim3(BB / 128, DD / 128, RR), 256, STG * STAGE_B>>>(eb);
    topk_fused<<<BB * RR, 256, 52224>>>(x, ew, eb, db, out);
}

// round 12
// speedup vs baseline: 1.1071x; 1.0774x over previous
#include <cuda_runtime.h>
#include <cuda_bf16.h>
#include <cuda_fp16.h>
#include <cstdint>

// Problem constants
#define BB 1024
#define RR 8
#define CC 1024
#define DD 16384
#define KK 32
#define THRC 48
#define MAXC 256
#define WINU 6

// ---------------- device scratch ----------------------------------------------
__device__ __nv_bfloat16 g_h[(size_t)BB * RR * DD];      // 256 MB (ranking only)
__device__ __half g_dwT[(size_t)RR * DD * CC];           // 256 MB fp16 [R,D,C]
__device__ __nv_bfloat16 g_xb[(size_t)BB * RR * CC];
__device__ __nv_bfloat16 g_ewb[(size_t)RR * DD * CC];

__device__ __forceinline__ uint32_t smem_u32(const void* p) {
    uint32_t a;
    asm("{ .reg .u64 t; cvta.to.shared.u64 t, %1; cvt.u32.u64 %0, t; }" : "=r"(a) : "l"(p));
    return a;
}

// ---------------- kernel 0: fused prep (conv_ew | transpose_dw->fp16 | conv_x) --
#define EW_BLOCKS ((int)(((size_t)RR * DD * CC / 4) / 256))     // 131072
#define TR_BLOCKS ((DD / 32) * (CC / 64) * RR)                  // 65536
#define X_BLOCKS  ((BB * RR * CC / 4) / 256)                    // 8192

__global__ __launch_bounds__(256) void prep_kernel(const float* __restrict__ ew,
                                                   const float* __restrict__ dw,
                                                   const float* __restrict__ x,
                                                   const float* __restrict__ db) {
    __shared__ float tile[32][65];
    int bid = blockIdx.x;
    int tid = threadIdx.x;

    if (bid < EW_BLOCKS) {
        size_t i = (size_t)bid * 256 + tid;
        float4 v = ((const float4*)ew)[i];
        unsigned short h[4];
        h[0] = __bfloat16_as_ushort(__float2bfloat16(v.x));
        h[1] = __bfloat16_as_ushort(__float2bfloat16(v.y));
        h[2] = __bfloat16_as_ushort(__float2bfloat16(v.z));
        h[3] = __bfloat16_as_ushort(__float2bfloat16(v.w));
        uint2 u = {(uint32_t)h[0] | ((uint32_t)h[1] << 16),
                   (uint32_t)h[2] | ((uint32_t)h[3] << 16)};
        ((uint2*)g_ewb)[i] = u;
    } else if (bid < EW_BLOCKS + TR_BLOCKS) {
        int bid2 = bid - EW_BLOCKS;
        int r   = bid2 >> 13;
        int rem = bid2 & 8191;
        int d0  = (rem & 511) * 32;
        int c0  = (rem >> 9) * 64;
        const float* src = dw + (size_t)r * CC * DD;
        __half* dst = g_dwT + (size_t)r * DD * CC;
        int tx = tid & 31, ty = tid >> 5;
#pragma unroll
        for (int i = 0; i < 64; i += 8)
            tile[tx][ty + i] = src[(size_t)(c0 + ty + i) * DD + d0 + tx];
        __syncthreads();
#pragma unroll
        for (int w = 0; w < 4; w++) {
            int uid = tid + w * 256;
            int drow = uid >> 5;
            int cp   = uid & 31;
            __half2 hv = __floats2half2_rn(tile[drow][2 * cp],
                                           tile[drow][2 * cp + 1]);
            *(__half2*)(dst + (size_t)(d0 + drow) * CC + c0 + 2 * cp) = hv;
        }
    } else {
        int bid2 = bid - (EW_BLOCKS + TR_BLOCKS);
        size_t i = (size_t)bid2 * 256 + tid;
        size_t e = i * 4;
        int c = (int)(e & (CC - 1));
        int r = (int)((e >> 10) & 7);
        float4 xv = ((const float4*)x)[i];
        float4 dv = *(const float4*)(db + r * CC + c);
        unsigned short h[4];
        h[0] = __bfloat16_as_ushort(__float2bfloat16(xv.x - dv.x));
        h[1] = __bfloat16_as_ushort(__float2bfloat16(xv.y - dv.y));
        h[2] = __bfloat16_as_ushort(__float2bfloat16(xv.z - dv.z));
        h[3] = __bfloat16_as_ushort(__float2bfloat16(xv.w - dv.w));
        uint2 u = {(uint32_t)h[0] | ((uint32_t)h[1] << 16),
                   (uint32_t)h[2] | ((uint32_t)h[3] << 16)};
        ((uint2*)g_xb)[i] = u;
    }
}

// ---------------- kernel 2: encode GEMM via mma.sync (bf16, fp32 accum) --------
#define GBK 64
#define KT (CC / GBK)
#define STG 3
#define ATILE_B 16384
#define STAGE_B 32768

__device__ __forceinline__ void ldm_x4(uint32_t addr, uint32_t& r0, uint32_t& r1,
                                       uint32_t& r2, uint32_t& r3) {
    asm volatile("ldmatrix.sync.aligned.m8n8.x4.shared.b16 {%0,%1,%2,%3}, [%4];"
                 : "=r"(r0), "=r"(r1), "=r"(r2), "=r"(r3) : "r"(addr));
}
__device__ __forceinline__ void mma16816(float* c, uint32_t a0, uint32_t a1,
                                         uint32_t a2, uint32_t a3,
                                         uint32_t b0, uint32_t b1) {
    asm volatile(
        "mma.sync.aligned.m16n8k16.row.col.f32.bf16.bf16.f32 "
        "{%0,%1,%2,%3}, {%4,%5,%6,%7}, {%8,%9}, {%0,%1,%2,%3};"
        : "+f"(c[0]), "+f"(c[1]), "+f"(c[2]), "+f"(c[3])
        : "r"(a0), "r"(a1), "r"(a2), "r"(a3), "r"(b0), "r"(b1));
}

__global__ __launch_bounds__(256, 2) void encode_gemm_mma(const float* __restrict__ eb) {
    extern __shared__ char smem[];
    uint32_t sb = smem_u32(smem);

    int tid = threadIdx.x, lane = tid & 31, wid = tid >> 5;
    int warp_m = wid >> 2;
    int warp_n = wid & 3;
    int mBase = blockIdx.x * 128;
    int nBase = blockIdx.y * 128;
    int r     = blockIdx.z;

    const __nv_bfloat16* Bb = g_ewb + (size_t)r * DD * CC;

    uint32_t soff[8];
    const __nv_bfloat16* gbase[8];
#pragma unroll
    for (int i = 0; i < 8; i++) {
        int uid = tid + i * 256;
        int row = (uid & 1023) >> 3;
        int u   = uid & 7;
        bool isA = uid < 1024;
        soff[i] = (isA ? 0u : (uint32_t)ATILE_B) +
                  (uint32_t)(row * 128 + ((u ^ (row & 7)) << 4));
        gbase[i] = isA ? (g_xb + ((size_t)(mBase + row) * RR + r) * CC + u * 8)
                       : (Bb + (size_t)(nBase + row) * CC + u * 8);
    }

    auto issue_stage = [&](int kt, int s) {
        uint32_t sbase = sb + s * STAGE_B;
        int k0 = kt * GBK;
#pragma unroll
        for (int i = 0; i < 8; i++) {
            uint32_t sa = sbase + soff[i];
            const void* g = (const void*)(gbase[i] + k0);
            asm volatile("cp.async.cg.shared.global [%0], [%1], 16;"
                         :: "r"(sa), "l"(g));
        }
        asm volatile("cp.async.commit_group;");
    };

    issue_stage(0, 0);
    issue_stage(1, 1);

    float acc[16][4];
#pragma unroll
    for (int i = 0; i < 16; i++)
#pragma unroll
        for (int j = 0; j < 4; j++) acc[i][j] = 0.f;

    int arow = warp_m * 64 + (lane & 15);
    int ab   = (lane >> 4) & 1;
    int nrow = warp_n * 32 + ((lane >> 4) << 3) + (lane & 7);
    int bb_  = (lane >> 3) & 1;

    int st = 0;
    for (int kt = 0; kt < KT; kt++) {
        asm volatile("cp.async.wait_group %0;" :: "n"(STG - 2));
        __syncthreads();
        int nxt = kt + STG - 1;
        int sNxt = st + (STG - 1); if (sNxt >= STG) sNxt -= STG;
        if (nxt < KT) issue_stage(nxt, sNxt);
        else asm volatile("cp.async.commit_group;");

        uint32_t sA = sb + st * STAGE_B;
        uint32_t sB = sA + ATILE_B;

#pragma unroll
        for (int ks = 0; ks < 4; ks++) {
            uint32_t bfr[8];
#pragma unroll
            for (int nfp = 0; nfp < 2; nfp++) {
                int rown = nrow + nfp * 16;
                int unit = ks * 2 + bb_;
                uint32_t addr = sB + rown * 128 + ((unit ^ (rown & 7)) << 4);
                ldm_x4(addr, bfr[nfp * 4 + 0], bfr[nfp * 4 + 1],
                             bfr[nfp * 4 + 2], bfr[nfp * 4 + 3]);
            }
#pragma unroll
            for (int mf = 0; mf < 4; mf++) {
                int rowm = arow + mf * 16;
                int unit = ks * 2 + ab;
                uint32_t addr = sA + rowm * 128 + ((unit ^ (rowm & 7)) << 4);
                uint32_t a0, a1, a2, a3;
                ldm_x4(addr, a0, a1, a2, a3);
#pragma unroll
                for (int nf = 0; nf < 4; nf++)
                    mma16816(acc[mf * 4 + nf], a0, a1, a2, a3,
                             bfr[nf * 2], bfr[nf * 2 + 1]);
            }
        }
        if (++st == STG) st = 0;
    }

    int trow = lane >> 2;
    int tcol = (lane & 3) * 2;
    const float* ebr = eb + (size_t)r * DD;
#pragma unroll
    for (int mf = 0; mf < 4; mf++) {
#pragma unroll
        for (int nf = 0; nf < 4; nf++) {
            int m = mBase + warp_m * 64 + mf * 16 + trow;
            int d = nBase + warp_n * 32 + nf * 8 + tcol;
            float2 ebv = *(const float2*)(ebr + d);
            __nv_bfloat16* h0 = g_h + (size_t)m * (RR * DD) + (size_t)r * DD + d;
            __nv_bfloat16* h1 = h0 + 8 * (size_t)(RR * DD);
            __nv_bfloat162 v0 = __floats2bfloat162_rn(acc[mf * 4 + nf][0] + ebv.x,
                                                      acc[mf * 4 + nf][1] + ebv.y);
            __nv_bfloat162 v1 = __floats2bfloat162_rn(acc[mf * 4 + nf][2] + ebv.x,
                                                      acc[mf * 4 + nf][3] + ebv.y);
            *(__nv_bfloat162*)h0 = v0;
            *(__nv_bfloat162*)h1 = v1;
        }
    }
}

// ---------------- kernel 3: fused select + refine + rank + decode --------------
// Latency-tolerant: batched prefetch (MLP 8) in both h passes; 23 KB smem
// (no keys array; pass B re-reads the L2-resident h row) -> 6 CTAs/SM.
__global__ __launch_bounds__(256, 6) void topk_fused(const float* __restrict__ x,
                                                     const float* __restrict__ ew,
                                                     const float* __restrict__ eb,
                                                     const float* __restrict__ db,
                                                     float* __restrict__ out) {
    __shared__ unsigned int hist[4096];     // 16 KB
    __shared__ float xcf[CC];               // 4 KB
    __shared__ unsigned int pk[256];        // 1 KB
    __shared__ unsigned long long skey[256];// 2 KB
    __shared__ unsigned int part[256];      // 1 KB
    __shared__ unsigned int s_thrbin, s_cnt;
    __shared__ float sv[KK];
    __shared__ int   si[KK];

    int row = blockIdx.x;
    int b_  = row >> 3;
    int r_  = row & 7;
    int tid = threadIdx.x;
    int lane = tid & 31, warp = tid >> 5;
    const uint32_t* hw = (const uint32_t*)(g_h + (size_t)row * DD);

    for (int i = tid; i < 4096; i += 256) hist[i] = 0;
    if (tid == 0) s_cnt = 0;
    __syncthreads();

    // ---- pass A: histogram with batched prefetch (8 independent loads) ----
#pragma unroll
    for (int bt = 0; bt < 4; bt++) {
        uint32_t v[8];
#pragma unroll
        for (int j = 0; j < 8; j++)
            v[j] = hw[tid + (bt * 8 + j) * 256];
#pragma unroll
        for (int j = 0; j < 8; j++) {
            unsigned short a = (unsigned short)(v[j] & 0xFFFFu);
            unsigned short b = (unsigned short)(v[j] >> 16);
            unsigned short ka = (a & 0x8000u) ? (unsigned short)~a : (unsigned short)(a | 0x8000u);
            unsigned short kb = (b & 0x8000u) ? (unsigned short)~b : (unsigned short)(b | 0x8000u);
            unsigned int ba = (unsigned int)(ka >> 4);
            unsigned int bbb = (unsigned int)(kb >> 4);
            unsigned int m1 = __match_any_sync(0xffffffffu, ba);
            if ((m1 & ((1u << lane) - 1u)) == 0u) atomicAdd(&hist[ba], __popc(m1));
            unsigned int m2 = __match_any_sync(0xffffffffu, bbb);
            if ((m2 & ((1u << lane) - 1u)) == 0u) atomicAdd(&hist[bbb], __popc(m2));
        }
    }
    __syncthreads();

    // ---- threshold scan ----
    unsigned int psum = 0;
#pragma unroll
    for (int j = 0; j < 16; j++) psum += hist[tid * 16 + j];
    part[tid] = psum;
    __syncthreads();

    if (warp == 0) {
        unsigned int pv[8], s8 = 0;
        int base = lane * 8;
#pragma unroll
        for (int j = 0; j < 8; j++) { pv[j] = part[base + j]; s8 += pv[j]; }
        unsigned int suf = s8;
#pragma unroll
        for (int off = 1; off < 32; off <<= 1) {
            unsigned int o = __shfl_down_sync(0xffffffffu, suf, off);
            if (lane + off < 32) suf += o;
        }
        unsigned int bal = __ballot_sync(0xffffffffu, suf >= THRC);
        int L = 31 - __clz((int)bal);
        if (lane == L) {
            unsigned int acc = suf - s8;
            int seg = base;
            for (int j = 7; j >= 0; j--) {
                if (acc + pv[j] >= THRC) { seg = base + j; break; }
                acc += pv[j];
            }
            int T = seg * 16;
            for (int b2 = seg * 16 + 15; b2 >= seg * 16; b2--) {
                if (acc + hist[b2] >= THRC) { T = b2; break; }
                acc += hist[b2];
            }
            s_thrbin = (unsigned int)T;
        }
    }
    __syncthreads();

    // ---- pass B: collect candidates (L2 re-read, batched); stage xcf ----
    unsigned int T = s_thrbin;
    const float* xr  = x  + (size_t)b_ * (RR * CC) + (size_t)r_ * CC;
    const float* dbr = db + r_ * CC;
    for (int c = tid; c < CC; c += 256)
        xcf[c] = xr[c] - dbr[c];
    pk[tid] = 0u;
    skey[tid] = 0ull;
    __syncthreads();

#pragma unroll
    for (int bt = 0; bt < 4; bt++) {
        uint32_t v[8];
#pragma unroll
        for (int j = 0; j < 8; j++)
            v[j] = hw[tid + (bt * 8 + j) * 256];
#pragma unroll
        for (int j = 0; j < 8; j++) {
            int i = tid + (bt * 8 + j) * 256;
            unsigned short a = (unsigned short)(v[j] & 0xFFFFu);
            unsigned short b = (unsigned short)(v[j] >> 16);
            unsigned short ka = (a & 0x8000u) ? (unsigned short)~a : (unsigned short)(a | 0x8000u);
            unsigned short kb = (b & 0x8000u) ? (unsigned short)~b : (unsigned short)(b | 0x8000u);
            if ((unsigned int)(ka >> 4) >= T) {
                unsigned int p = atomicAdd(&s_cnt, 1u);
                if (p < MAXC) pk[p] = ((unsigned int)ka << 16) | (unsigned int)(2 * i);
            }
            if ((unsigned int)(kb >> 4) >= T) {
                unsigned int p = atomicAdd(&s_cnt, 1u);
                if (p < MAXC) pk[p] = ((unsigned int)kb << 16) | (unsigned int)(2 * i + 1);
            }
        }
    }
    __syncthreads();

    // ---- bitonic sort 256 packed u32 ascending ----
    for (int k = 2; k <= 256; k <<= 1) {
        for (int j2 = k >> 1; j2 > 0; j2 >>= 1) {
            int i = tid, ixj = i ^ j2;
            if (ixj > i) {
                unsigned int ki = pk[i], kj = pk[ixj];
                bool up = ((i & k) == 0);
                if ((ki > kj) == up) { pk[i] = kj; pk[ixj] = ki; }
            }
            __syncthreads();
        }
    }

    unsigned int k32 = pk[256 - KK] >> 16;
    unsigned int t16 = (k32 > WINU) ? (k32 - WINU) : 0u;

    const float* ewr = ew + (size_t)r_ * DD * CC;

    // ---- key-gated compensated refine ----
    for (int jj = warp; jj < 256; jj += 8) {
        unsigned int p = pk[255 - jj];
        if (p == 0u || (p >> 16) < t16) continue;
        int d = (int)(p & 0xFFFFu);
        const float* wv = ewr + (size_t)d * CC;
        float s = 0.f, comp = 0.f;
#pragma unroll 4
        for (int c = lane; c < CC; c += 32) {
            float xv = xcf[c];
            float wf = __ldg(wv + c);
            float pr = __fmul_rn(xv, wf);
            float e  = __fmaf_rn(xv, wf, -pr);
            float t  = __fadd_rn(s, pr);
            float z  = __fsub_rn(t, s);
            float lo = __fadd_rn(__fsub_rn(s, __fsub_rn(t, z)), __fsub_rn(pr, z));
            s = t;
            comp = __fadd_rn(comp, __fadd_rn(lo, e));
        }
        double a = (double)s + (double)comp;
#pragma unroll
        for (int off = 16; off > 0; off >>= 1)
            a += __shfl_down_sync(0xffffffffu, a, off);
        if (lane == 0) {
            double v = a + (double)eb[(size_t)r_ * DD + d];
            unsigned long long ub = (unsigned long long)__double_as_longlong(v);
            unsigned long long o = (ub >> 63) ? ~ub : (ub | 0x8000000000000000ull);
            o = (o & ~0x3FFFull) | (unsigned long long)(16383 - d);
            skey[255 - jj] = o;
        }
    }
    __syncthreads();

    // ---- bitonic sort 256 u64 keys ascending ----
    for (int k = 2; k <= 256; k <<= 1) {
        for (int j2 = k >> 1; j2 > 0; j2 >>= 1) {
            int i = tid, ixj = i ^ j2;
            if (ixj > i) {
                unsigned long long ki = skey[i], kj = skey[ixj];
                bool up = ((i & k) == 0);
                if ((ki > kj) == up) { skey[i] = kj; skey[ixj] = ki; }
            }
            __syncthreads();
        }
    }

    if (tid < KK) {
        unsigned long long o = skey[255 - tid];
        int d = 16383 - (int)(o & 0x3FFFull);
        unsigned long long vb = o & ~0x3FFFull;
        unsigned long long ub = (vb >> 63) ? (vb & 0x7FFFFFFFFFFFFFFFull) : ~vb;
        double v = __longlong_as_double((long long)ub);
        sv[tid] = fmaxf((float)v, 0.f);
        si[tid] = d;
    }
    __syncthreads();

    // ---- fused sparse decode from fp16 dwT ----
    const __half* base = g_dwT + (size_t)r_ * DD * CC;
    float4 acc4 = *(const float4*)(dbr + tid * 4);
#pragma unroll 8
    for (int t = 0; t < KK; t++) {
        float v = sv[t];
        const __half2* wp = (const __half2*)(base + (size_t)si[t] * CC + tid * 4);
        __half2 w01 = wp[0];
        __half2 w23 = wp[1];
        float2 f01 = __half22float2(w01);
        float2 f23 = __half22float2(w23);
        acc4.x += v * f01.x;
        acc4.y += v * f01.y;
        acc4.z += v * f23.x;
        acc4.w += v * f23.y;
    }
    *(float4*)(out + (size_t)b_ * (RR * CC) + r_ * CC + tid * 4) = acc4;
}

// ---------------- launch (single stream, 3 kernels) ------------------------------
extern "C" void kernel_launch(void* const* d_in, const int* in_sizes, int n_in,
                              void* d_out, int out_size) {
    const float* x  = (const float*)d_in[0];
    const float* ew = (const float*)d_in[1];
    const float* eb = (const float*)d_in[2];
    const float* dw = (const float*)d_in[3];
    const float* db = (const float*)d_in[4];
    float* out = (float*)d_out;

    cudaFuncSetAttribute(encode_gemm_mma,
                         cudaFuncAttributeMaxDynamicSharedMemorySize, STG * STAGE_B);

    prep_kernel<<<EW_BLOCKS + TR_BLOCKS + X_BLOCKS, 256>>>(ew, dw, x, db);
    encode_gemm_mma<<<dim3(BB / 128, DD / 128, RR), 256, STG * STAGE_B>>>(eb);
    topk_fused<<<BB * RR, 256>>>(x, ew, eb, db, out);
}